// round 1
// baseline (speedup 1.0000x reference)
#include <cuda_runtime.h>
#include <math.h>
#include <stdint.h>

// Problem dims
#define B_   4
#define S_   512
#define H_   2048
#define E_   16
#define D_   128
#define GH_  2048
#define G3_  6144
#define NTOK 2048   // B_*S_

// Output layout (flat f32 concat, reference return order)
#define O_MULT 0
#define O_SEL  4096
#define O_EXPR 8192
#define O_HN   4202496
#define O_PEN  4210688
#define O_COS  4210689
#define O_LOSS 4243457

// -------- device scratch (static globals: allocation-free) --------
__device__ float    g_xi[NTOK * G3_];      // 50.3 MB: input-proj gates per token
__device__ float    g_hs[NTOK * GH_];      // 16.8 MB: all GRU hidden states
__device__ float    g_hbuf[2 * B_ * GH_];  // double-buffered h
__device__ float    g_pen[NTOK];
__device__ float    g_scal[32];            // [0]=penalty, [1..16]=adjustment
__device__ float    g_losspart[1024];
__device__ unsigned g_ctr;                 // grid barrier counter

// -------- helpers --------
__device__ __forceinline__ float wsum(float v) {
#pragma unroll
    for (int o = 16; o > 0; o >>= 1) v += __shfl_xor_sync(0xffffffffu, v, o);
    return v;
}

__device__ __forceinline__ void gsync(unsigned target) {
    __threadfence();
    __syncthreads();
    if (threadIdx.x == 0) {
        atomicAdd(&g_ctr, 1u);
        volatile unsigned* p = &g_ctr;
        while (*p < target) {}
    }
    __syncthreads();
}

__device__ __forceinline__ void fma4(float4& a, const float4 w,
                                     const float4 h0, const float4 h1,
                                     const float4 h2, const float4 h3) {
    a.x += w.x*h0.x + w.y*h1.x + w.z*h2.x + w.w*h3.x;
    a.y += w.x*h0.y + w.y*h1.y + w.z*h2.y + w.w*h3.y;
    a.z += w.x*h0.z + w.y*h1.z + w.z*h2.z + w.w*h3.z;
    a.w += w.x*h0.w + w.y*h1.w + w.z*h2.w + w.w*h3.w;
}

// -------- init: h0 <- hn, barrier counter <- 0 --------
__global__ void init_kernel(const float* __restrict__ hn) {
    int i = blockIdx.x * 256 + threadIdx.x;
    if (i == 0) g_ctr = 0u;
    if (i < B_ * GH_) g_hbuf[i] = hn[i];
}

// -------- generic SGEMM: C[M,N] = A[M,K] * B --------
// OPB==0: B stored [K,N] row-major.  OPB==1: B stored [N,K] row-major (B^T).
// BM=128, BN=64, BK=16, 256 threads, 8x4 microtile. Dims assumed divisible.
template <int OPB>
__global__ void __launch_bounds__(256) sgemm_kernel(
    const float* __restrict__ A, const float* __restrict__ Bm,
    float* __restrict__ C, int M, int N, int K)
{
    __shared__ float As[16][128];
    __shared__ float Bs[16][64];
    const int m0 = blockIdx.y * 128;
    const int n0 = blockIdx.x * 64;
    const int t  = threadIdx.x;
    const int tx = t % 16;       // 4 cols
    const int ty = t / 16;       // 8 rows
    float acc[8][4] = {};

    for (int k0 = 0; k0 < K; k0 += 16) {
        // A tile: 128x16 = 512 float4, 2 per thread
#pragma unroll
        for (int f = 0; f < 2; f++) {
            int idx = t + f * 256;
            int m   = idx % 128;
            int kb  = idx / 128;            // 0..3
            float4 v = *reinterpret_cast<const float4*>(&A[(size_t)(m0 + m) * K + k0 + kb * 4]);
            As[kb*4+0][m] = v.x; As[kb*4+1][m] = v.y;
            As[kb*4+2][m] = v.z; As[kb*4+3][m] = v.w;
        }
        // B tile: 16x64 = 256 float4, 1 per thread
        if (OPB == 0) {
            int n4 = t % 16, kk = t / 16;
            float4 v = *reinterpret_cast<const float4*>(&Bm[(size_t)(k0 + kk) * N + n0 + n4 * 4]);
            *reinterpret_cast<float4*>(&Bs[kk][n4 * 4]) = v;
        } else {
            int n = t % 64, kq = t / 64;    // kq 0..3
            float4 v = *reinterpret_cast<const float4*>(&Bm[(size_t)(n0 + n) * K + k0 + kq * 4]);
            Bs[kq*4+0][n] = v.x; Bs[kq*4+1][n] = v.y;
            Bs[kq*4+2][n] = v.z; Bs[kq*4+3][n] = v.w;
        }
        __syncthreads();
#pragma unroll
        for (int kk = 0; kk < 16; kk++) {
            float a[8], bb[4];
#pragma unroll
            for (int i = 0; i < 8; i++) a[i] = As[kk][ty * 8 + i];
#pragma unroll
            for (int j = 0; j < 4; j++) bb[j] = Bs[kk][tx * 4 + j];
#pragma unroll
            for (int i = 0; i < 8; i++)
#pragma unroll
                for (int j = 0; j < 4; j++)
                    acc[i][j] += a[i] * bb[j];
        }
        __syncthreads();
    }
#pragma unroll
    for (int i = 0; i < 8; i++) {
        float4 v = make_float4(acc[i][0], acc[i][1], acc[i][2], acc[i][3]);
        *reinterpret_cast<float4*>(&C[(size_t)(m0 + ty * 8 + i) * N + n0 + tx * 4]) = v;
    }
}

// -------- persistent GRU recurrence --------
// One warp handles all 3 gate dots + h-update for its column j (no cross-block
// gate exchange). Double-buffered h => exactly one grid-sync per step.
__global__ void __launch_bounds__(256) gru_kernel(const float* __restrict__ w_hh,
                                                  float* __restrict__ out_hn) {
    __shared__ float4 h_s[GH_];   // h_s[k] = (h[0][k],h[1][k],h[2][k],h[3][k])
    const int t      = threadIdx.x;
    const int lane   = t & 31;
    const int warp   = t >> 5;
    const int nb     = gridDim.x;
    const int gwarp  = blockIdx.x * 8 + warp;
    const int nwarps = nb * 8;
    unsigned target = 0;

    for (int step = 0; step < S_; step++) {
        if (step > 0) { target += nb; gsync(target); }
        const float* hsrc = g_hbuf + (step & 1) * (B_ * GH_);
        for (int k = t; k < GH_; k += 256) {
            h_s[k] = make_float4(__ldcg(hsrc + k),
                                 __ldcg(hsrc + GH_ + k),
                                 __ldcg(hsrc + 2 * GH_ + k),
                                 __ldcg(hsrc + 3 * GH_ + k));
        }
        __syncthreads();
        float* hdst = g_hbuf + ((step + 1) & 1) * (B_ * GH_);

        for (int j = gwarp; j < GH_; j += nwarps) {
            const float* wr = w_hh + (size_t)j * GH_;
            const float* wz = w_hh + (size_t)(GH_ + j) * GH_;
            const float* wn = w_hh + (size_t)(2 * GH_ + j) * GH_;
            float4 ar = make_float4(0.f, 0.f, 0.f, 0.f);
            float4 az = ar, an = ar;
            for (int k = lane * 4; k < GH_; k += 128) {
                float4 r4 = *reinterpret_cast<const float4*>(wr + k);
                float4 z4 = *reinterpret_cast<const float4*>(wz + k);
                float4 n4 = *reinterpret_cast<const float4*>(wn + k);
                float4 h0 = h_s[k], h1 = h_s[k + 1], h2 = h_s[k + 2], h3 = h_s[k + 3];
                fma4(ar, r4, h0, h1, h2, h3);
                fma4(az, z4, h0, h1, h2, h3);
                fma4(an, n4, h0, h1, h2, h3);
            }
            ar.x = wsum(ar.x); ar.y = wsum(ar.y); ar.z = wsum(ar.z); ar.w = wsum(ar.w);
            az.x = wsum(az.x); az.y = wsum(az.y); az.z = wsum(az.z); az.w = wsum(az.w);
            an.x = wsum(an.x); an.y = wsum(an.y); an.z = wsum(an.z); an.w = wsum(an.w);
            if (lane == 0) {
                float AR[4] = {ar.x, ar.y, ar.z, ar.w};
                float AZ[4] = {az.x, az.y, az.z, az.w};
                float AN[4] = {an.x, an.y, an.z, an.w};
                float4 hj = h_s[j];
                float HO[4] = {hj.x, hj.y, hj.z, hj.w};
#pragma unroll
                for (int b = 0; b < 4; b++) {
                    size_t base = (size_t)(b * S_ + step) * G3_ + j;
                    float xr = g_xi[base];
                    float xz = g_xi[base + GH_];
                    float xn = g_xi[base + 2 * GH_];
                    float r = 1.f / (1.f + expf(-(xr + AR[b])));
                    float z = 1.f / (1.f + expf(-(xz + AZ[b])));
                    float n = tanhf(xn + r * AN[b]);
                    float hv = (1.f - z) * n + z * HO[b];
                    __stcg(hdst + b * GH_ + j, hv);
                    g_hs[(size_t)(b * S_ + step) * GH_ + j] = hv;
                }
            }
        }
    }
    target += nb; gsync(target);
    if (blockIdx.x == 0) {
        const float* hf = g_hbuf;   // final h in buffer 0 (512 even)
        for (int i = t; i < B_ * GH_; i += 256) out_hn[i] = __ldcg(hf + i);
    }
}

// -------- per-token: normalize rout, gram penalty, cosine sims --------
__global__ void __launch_bounds__(128) token_kernel(const float* __restrict__ expr,
                                                    float* __restrict__ cosO) {
    const int token = blockIdx.x;
    const int t = threadIdx.x, lane = t & 31, warp = t >> 5;
    __shared__ float sv[16 * 132];
    __shared__ float gm[16][17];
    __shared__ float pen_s[16];
    const float* rout = g_hs + (size_t)token * GH_;

    for (int e = warp; e < 16; e += 4) {
        float s = 0.f;
        for (int d = lane; d < 128; d += 32) { float v = rout[e * 128 + d]; s += v * v; }
        s = wsum(s);
        float inv = 1.f / fmaxf(sqrtf(s), 1e-12f);
        for (int d = lane; d < 128; d += 32) sv[e * 132 + d] = rout[e * 128 + d] * inv;
    }
    __syncthreads();
    for (int p = t; p < 256; p += 128) {
        int e = p >> 4, f = p & 15;
        float s = 0.f;
#pragma unroll 8
        for (int k = 0; k < 128; k++) s += sv[e * 132 + k] * sv[f * 132 + k];
        gm[e][f] = s;
    }
    __syncthreads();
    if (t < 16) {
        float s2 = 0.f;
        for (int f = 0; f < 16; f++) {
            float d = gm[t][f] - (t == f ? 1.f : 0.f);
            s2 += d * d;
        }
        float nrm = fmaxf(sqrtf(s2), 1e-12f);
        pen_s[t] = s2 / (nrm * nrm);
    }
    __syncthreads();
    if (t == 0) {
        float s = 0.f;
        for (int e = 0; e < 16; e++) s += pen_s[e];
        g_pen[token] = s;
    }
    for (int e = warp; e < 16; e += 4) {
        float dot = 0.f, ss = 0.f, rs = 0.f;
        for (int d = lane; d < 128; d += 32) {
            float ev = expr[(size_t)token * GH_ + e * 128 + d];
            float rv = sv[e * 132 + d];
            dot += ev * rv; ss += ev * ev; rs += rv * rv;
        }
        dot = wsum(dot); ss = wsum(ss); rs = wsum(rs);
        if (lane == 0) {
            float en = fmaxf(sqrtf(ss), 1e-8f);
            float rn = fmaxf(sqrtf(rs), 1e-8f);
            cosO[token * 16 + e] = 1.f - dot / (en * rn);
        }
    }
}

// -------- penalty mean + load-balance adjustment --------
__global__ void finalize_kernel(const float* __restrict__ ema, float* __restrict__ out) {
    __shared__ float red[256];
    int t = threadIdx.x;
    float s = 0.f;
    for (int i = t; i < NTOK; i += 256) s += g_pen[i];
    red[t] = s; __syncthreads();
    for (int o = 128; o > 0; o >>= 1) { if (t < o) red[t] += red[t + o]; __syncthreads(); }
    if (t == 0) {
        float pen = red[0] / (float)NTOK;
        g_scal[0] = pen;
        out[O_PEN] = pen;
        float tot = 0.f;
        for (int e = 0; e < 16; e++) tot += ema[e];
        for (int e = 0; e < 16; e++) {
            float sc = (tot > 0.f) ? ema[e] / fmaxf(tot, 1e-12f) : 0.f;
            g_scal[1 + e] = sc * 0.01f * 16.f;
        }
    }
}

// -------- top-2 + softmax + adjustment --------
__global__ void topk_kernel(const float* __restrict__ cosv, float* __restrict__ out) {
    int token = blockIdx.x * blockDim.x + threadIdx.x;
    if (token >= NTOK) return;
    float mul = 1.f + g_scal[0];
    float dv[16];
#pragma unroll
    for (int e = 0; e < 16; e++) dv[e] = cosv[token * 16 + e] * mul;
    int i0 = 0; float v0 = dv[0];
#pragma unroll
    for (int e = 1; e < 16; e++) if (dv[e] > v0) { v0 = dv[e]; i0 = e; }
    int i1 = (i0 == 0) ? 1 : 0; float v1 = dv[i1];
#pragma unroll
    for (int e = 0; e < 16; e++) if (e != i0 && dv[e] > v1) { v1 = dv[e]; i1 = e; }
    float e1  = expf(v1 - v0);
    float inv = 1.f / (1.f + e1);
    out[O_MULT + token * 2 + 0] = inv - g_scal[1 + i0];
    out[O_MULT + token * 2 + 1] = e1 * inv - g_scal[1 + i1];
    out[O_SEL + token * 2 + 0] = (float)i0;
    out[O_SEL + token * 2 + 1] = (float)i1;
}

// -------- expression loss: mean((W^T W - I)^2) --------
__global__ void __launch_bounds__(256) wloss_kernel(const float* __restrict__ W) {
    __shared__ float Is[16][64];
    __shared__ float Js[16][64];
    const int i0 = blockIdx.y * 64, j0 = blockIdx.x * 64;
    const int t = threadIdx.x, tx = t % 16, ty = t / 16;
    const int n4 = t % 16, kk = t / 16;
    float acc[4][4] = {};
    for (int k0 = 0; k0 < GH_; k0 += 16) {
        const float* rowp = W + (size_t)(k0 + kk) * GH_;
        *reinterpret_cast<float4*>(&Is[kk][n4 * 4]) =
            *reinterpret_cast<const float4*>(rowp + i0 + n4 * 4);
        *reinterpret_cast<float4*>(&Js[kk][n4 * 4]) =
            *reinterpret_cast<const float4*>(rowp + j0 + n4 * 4);
        __syncthreads();
#pragma unroll
        for (int k = 0; k < 16; k++) {
            float a[4], b[4];
#pragma unroll
            for (int i = 0; i < 4; i++) a[i] = Is[k][ty * 4 + i];
#pragma unroll
            for (int j = 0; j < 4; j++) b[j] = Js[k][tx * 4 + j];
#pragma unroll
            for (int i = 0; i < 4; i++)
#pragma unroll
                for (int j = 0; j < 4; j++)
                    acc[i][j] += a[i] * b[j];
        }
        __syncthreads();
    }
    float s = 0.f;
#pragma unroll
    for (int i = 0; i < 4; i++)
#pragma unroll
        for (int j = 0; j < 4; j++) {
            int gi = i0 + ty * 4 + i, gj = j0 + tx * 4 + j;
            float d = acc[i][j] - (gi == gj ? 1.f : 0.f);
            s += d * d;
        }
    __shared__ float red[256];
    red[t] = s; __syncthreads();
    for (int o = 128; o > 0; o >>= 1) { if (t < o) red[t] += red[t + o]; __syncthreads(); }
    if (t == 0) g_losspart[blockIdx.y * 32 + blockIdx.x] = red[0];
}

__global__ void wloss_reduce_kernel(float* __restrict__ out) {
    __shared__ float red[256];
    int t = threadIdx.x;
    float s = 0.f;
    for (int i = t; i < 1024; i += 256) s += g_losspart[i];
    red[t] = s; __syncthreads();
    for (int o = 128; o > 0; o >>= 1) { if (t < o) red[t] += red[t + o]; __syncthreads(); }
    if (t == 0) out[O_LOSS] = red[0] / ((float)GH_ * (float)GH_);
}

// -------- host --------
extern "C" void kernel_launch(void* const* d_in, const int* in_sizes, int n_in,
                              void* d_out, int out_size) {
    const float* x      = (const float*)d_in[0];
    const float* hn     = (const float*)d_in[1];
    const float* w_ih   = (const float*)d_in[2];
    const float* w_hh   = (const float*)d_in[3];
    const float* w_expr = (const float*)d_in[4];
    const float* ema    = (const float*)d_in[5];
    float* out = (float*)d_out;

    void* p = 0;
    cudaGetSymbolAddress(&p, g_xi);
    float* xi = (float*)p;

    int sm = 0;
    cudaDeviceGetAttribute(&sm, cudaDevAttrMultiProcessorCount, 0);
    if (sm <= 0) sm = 132;

    init_kernel<<<32, 256>>>(hn);

    dim3 gx(G3_ / 64, NTOK / 128);
    sgemm_kernel<1><<<gx, 256>>>(x, w_ih, xi, NTOK, G3_, H_);

    dim3 ge(GH_ / 64, NTOK / 128);
    sgemm_kernel<0><<<ge, 256>>>(x, w_expr, out + O_EXPR, NTOK, GH_, H_);

    gru_kernel<<<sm, 256>>>(w_hh, out + O_HN);

    token_kernel<<<NTOK, 128>>>(out + O_EXPR, out + O_COS);
    finalize_kernel<<<1, 256>>>(ema, out);
    topk_kernel<<<8, 256>>>(out + O_COS, out);

    wloss_kernel<<<dim3(32, 32), 256>>>(w_expr);
    wloss_reduce_kernel<<<1, 256>>>(out);
}

// round 2
// speedup vs baseline: 1.7749x; 1.7749x over previous
#include <cuda_runtime.h>
#include <math.h>
#include <stdint.h>

// Problem dims
#define B_   4
#define S_   512
#define H_   2048
#define E_   16
#define D_   128
#define GH_  2048
#define G3_  6144
#define NTOK 2048   // B_*S_

// Output layout (flat f32 concat, reference return order)
#define O_MULT 0
#define O_SEL  4096
#define O_EXPR 8192
#define O_HN   4202496
#define O_PEN  4210688
#define O_COS  4210689
#define O_LOSS 4243457

// -------- device scratch (static globals: allocation-free) --------
__device__ float    g_xi[NTOK * G3_];      // 50.3 MB
__device__ float    g_hs[NTOK * GH_];      // 16.8 MB
__device__ float    g_hbuf[2 * B_ * GH_];
__device__ float    g_pen[NTOK];
__device__ float    g_scal[32];
__device__ float    g_losspart[256];
__device__ unsigned g_ctr;

// -------- helpers --------
__device__ __forceinline__ float wsum(float v) {
#pragma unroll
    for (int o = 16; o > 0; o >>= 1) v += __shfl_xor_sync(0xffffffffu, v, o);
    return v;
}

__device__ __forceinline__ uint64_t pk2(float lo, float hi) {
    uint64_t r; asm("mov.b64 %0,{%1,%2};" : "=l"(r) : "f"(lo), "f"(hi)); return r;
}
__device__ __forceinline__ float2 upk2(uint64_t v) {
    float2 r; asm("mov.b64 {%0,%1}, %2;" : "=f"(r.x), "=f"(r.y) : "l"(v)); return r;
}
__device__ __forceinline__ void fma2(uint64_t& d, uint64_t a, uint64_t b) {
    asm("fma.rn.f32x2 %0, %1, %2, %3;" : "=l"(d) : "l"(a), "l"(b), "l"(d));
}

__device__ __forceinline__ void gsync(unsigned target) {
    __threadfence();
    __syncthreads();
    if (threadIdx.x == 0) {
        atomicAdd(&g_ctr, 1u);
        volatile unsigned* p = &g_ctr;
        while (*p < target) {}
    }
    __syncthreads();
}

// -------- init --------
__global__ void init_kernel(const float* __restrict__ hn) {
    int i = blockIdx.x * 256 + threadIdx.x;
    if (i == 0) g_ctr = 0u;
    if (i < B_ * GH_) g_hbuf[i] = hn[i];
}

// ================= SGEMM: C[M,N] = opA(A) * opB(B) =================
// OPA==0: A[M,K] row-major.  OPA==1: A[K,M] row-major (A^T effective).
// OPB==0: B[K,N] row-major.  OPB==1: B[N,K] row-major (B^T effective).
// EPI==0: store C.  EPI==1: wloss reduce sum((C - I)^2) -> g_losspart.
// Tile 128x128x16, 256 threads, 8x8 microtile, packed fma.rn.f32x2.
template <int OPA, int OPB, int EPI>
__global__ void __launch_bounds__(256, 2) sgemm2_kernel(
    const float* __restrict__ A, const float* __restrict__ Bm,
    float* __restrict__ C, int M, int N, int K)
{
    __shared__ float As[16][128];
    __shared__ float Bs[16][128];
    const int m0 = blockIdx.y * 128;
    const int n0 = blockIdx.x * 128;
    const int t  = threadIdx.x;
    const int tx = t & 15;
    const int ty = t >> 4;

    uint64_t acc2[8][4];
#pragma unroll
    for (int i = 0; i < 8; i++)
#pragma unroll
        for (int j = 0; j < 4; j++) acc2[i][j] = 0ull;

    for (int k0 = 0; k0 < K; k0 += 16) {
        // ---- A tile -> As[k][m] ----
        if (OPA == 0) {
            int m  = t & 127;
            int kq = t >> 7;   // 0..1
#pragma unroll
            for (int f = 0; f < 2; f++) {
                int koff = (kq + 2 * f) * 4;
                float4 v = *reinterpret_cast<const float4*>(
                    &A[(size_t)(m0 + m) * K + k0 + koff]);
                As[koff + 0][m] = v.x; As[koff + 1][m] = v.y;
                As[koff + 2][m] = v.z; As[koff + 3][m] = v.w;
            }
        } else {
            int kk = t >> 5;   // 0..7
            int m4 = t & 31;
#pragma unroll
            for (int f = 0; f < 2; f++) {
                float4 v = *reinterpret_cast<const float4*>(
                    &A[(size_t)(k0 + kk + 8 * f) * M + m0 + m4 * 4]);
                *reinterpret_cast<float4*>(&As[kk + 8 * f][m4 * 4]) = v;
            }
        }
        // ---- B tile -> Bs[k][n] ----
        if (OPB == 0) {
            int kk = t >> 5;
            int n4 = t & 31;
#pragma unroll
            for (int f = 0; f < 2; f++) {
                float4 v = *reinterpret_cast<const float4*>(
                    &Bm[(size_t)(k0 + kk + 8 * f) * N + n0 + n4 * 4]);
                *reinterpret_cast<float4*>(&Bs[kk + 8 * f][n4 * 4]) = v;
            }
        } else {
            int n  = t & 127;
            int kq = t >> 7;
#pragma unroll
            for (int f = 0; f < 2; f++) {
                int koff = (kq + 2 * f) * 4;
                float4 v = *reinterpret_cast<const float4*>(
                    &Bm[(size_t)(n0 + n) * K + k0 + koff]);
                Bs[koff + 0][n] = v.x; Bs[koff + 1][n] = v.y;
                Bs[koff + 2][n] = v.z; Bs[koff + 3][n] = v.w;
            }
        }
        __syncthreads();
#pragma unroll
        for (int k = 0; k < 16; k++) {
            float4 a0 = *reinterpret_cast<const float4*>(&As[k][ty * 4]);
            float4 a1 = *reinterpret_cast<const float4*>(&As[k][64 + ty * 4]);
            float4 b0 = *reinterpret_cast<const float4*>(&Bs[k][tx * 4]);
            float4 b1 = *reinterpret_cast<const float4*>(&Bs[k][64 + tx * 4]);
            uint64_t bp[4] = { pk2(b0.x, b0.y), pk2(b0.z, b0.w),
                               pk2(b1.x, b1.y), pk2(b1.z, b1.w) };
            float av[8] = { a0.x, a0.y, a0.z, a0.w, a1.x, a1.y, a1.z, a1.w };
#pragma unroll
            for (int i = 0; i < 8; i++) {
                uint64_t ap = pk2(av[i], av[i]);
#pragma unroll
                for (int j = 0; j < 4; j++) fma2(acc2[i][j], ap, bp[j]);
            }
        }
        __syncthreads();
    }

    if (EPI == 0) {
#pragma unroll
        for (int i = 0; i < 8; i++) {
            int mrow = m0 + ((i < 4) ? (ty * 4 + i) : (64 + ty * 4 + i - 4));
            float2 c0 = upk2(acc2[i][0]), c1 = upk2(acc2[i][1]);
            float2 c2 = upk2(acc2[i][2]), c3 = upk2(acc2[i][3]);
            *reinterpret_cast<float4*>(&C[(size_t)mrow * N + n0 + tx * 4]) =
                make_float4(c0.x, c0.y, c1.x, c1.y);
            *reinterpret_cast<float4*>(&C[(size_t)mrow * N + n0 + 64 + tx * 4]) =
                make_float4(c2.x, c2.y, c3.x, c3.y);
        }
    } else {
        float s = 0.f;
#pragma unroll
        for (int i = 0; i < 8; i++) {
            int gi = m0 + ((i < 4) ? (ty * 4 + i) : (64 + ty * 4 + i - 4));
#pragma unroll
            for (int j = 0; j < 4; j++) {
                float2 c = upk2(acc2[i][j]);
                int gj0 = n0 + ((j < 2) ? (tx * 4 + j * 2) : (64 + tx * 4 + (j - 2) * 2));
                float d0 = c.x - (gi == gj0 ? 1.f : 0.f);
                float d1 = c.y - (gi == gj0 + 1 ? 1.f : 0.f);
                s += d0 * d0 + d1 * d1;
            }
        }
        __shared__ float red[256];
        red[t] = s; __syncthreads();
        for (int o = 128; o > 0; o >>= 1) { if (t < o) red[t] += red[t + o]; __syncthreads(); }
        if (t == 0) g_losspart[blockIdx.y * gridDim.x + blockIdx.x] = red[0];
    }
}

// ================= persistent GRU recurrence =================
__global__ void __launch_bounds__(512) gru_kernel(const float* __restrict__ w_hh,
                                                  float* __restrict__ out_hn) {
    __shared__ float4 h_s[GH_];
    const int t      = threadIdx.x;
    const int lane   = t & 31;
    const int warp   = t >> 5;
    const int nb     = gridDim.x;
    const int gwarp  = blockIdx.x * 16 + warp;
    const int nwarps = nb * 16;
    unsigned target = 0;

    for (int step = 0; step < S_; step++) {
        if (step > 0) { target += nb; gsync(target); }
        const float* hsrc = g_hbuf + (step & 1) * (B_ * GH_);
        for (int k = t; k < GH_; k += 512) {
            h_s[k] = make_float4(__ldcg(hsrc + k),
                                 __ldcg(hsrc + GH_ + k),
                                 __ldcg(hsrc + 2 * GH_ + k),
                                 __ldcg(hsrc + 3 * GH_ + k));
        }
        __syncthreads();
        float* hdst = g_hbuf + ((step + 1) & 1) * (B_ * GH_);

        for (int j = gwarp; j < GH_; j += nwarps) {
            // prefetch the 12 xi scalars (3 gates x 4 batch) into lanes 0..11
            float xiv = 0.f;
            if (lane < 12)
                xiv = g_xi[(size_t)((lane & 3) * S_ + step) * G3_ + (lane >> 2) * GH_ + j];

            const float* wr = w_hh + (size_t)j * GH_;
            const float* wz = w_hh + (size_t)(GH_ + j) * GH_;
            const float* wn = w_hh + (size_t)(2 * GH_ + j) * GH_;
            float4 ar = make_float4(0.f, 0.f, 0.f, 0.f);
            float4 az = ar, an = ar;
            for (int k = lane * 4; k < GH_; k += 128) {
                float4 r4 = *reinterpret_cast<const float4*>(wr + k);
                float4 z4 = *reinterpret_cast<const float4*>(wz + k);
                float4 n4 = *reinterpret_cast<const float4*>(wn + k);
                float4 h0 = h_s[k], h1 = h_s[k + 1], h2 = h_s[k + 2], h3 = h_s[k + 3];
                ar.x += r4.x*h0.x + r4.y*h1.x + r4.z*h2.x + r4.w*h3.x;
                ar.y += r4.x*h0.y + r4.y*h1.y + r4.z*h2.y + r4.w*h3.y;
                ar.z += r4.x*h0.z + r4.y*h1.z + r4.z*h2.z + r4.w*h3.z;
                ar.w += r4.x*h0.w + r4.y*h1.w + r4.z*h2.w + r4.w*h3.w;
                az.x += z4.x*h0.x + z4.y*h1.x + z4.z*h2.x + z4.w*h3.x;
                az.y += z4.x*h0.y + z4.y*h1.y + z4.z*h2.y + z4.w*h3.y;
                az.z += z4.x*h0.z + z4.y*h1.z + z4.z*h2.z + z4.w*h3.z;
                az.w += z4.x*h0.w + z4.y*h1.w + z4.z*h2.w + z4.w*h3.w;
                an.x += n4.x*h0.x + n4.y*h1.x + n4.z*h2.x + n4.w*h3.x;
                an.y += n4.x*h0.y + n4.y*h1.y + n4.z*h2.y + n4.w*h3.y;
                an.z += n4.x*h0.z + n4.y*h1.z + n4.z*h2.z + n4.w*h3.z;
                an.w += n4.x*h0.w + n4.y*h1.w + n4.z*h2.w + n4.w*h3.w;
            }
            ar.x = wsum(ar.x); ar.y = wsum(ar.y); ar.z = wsum(ar.z); ar.w = wsum(ar.w);
            az.x = wsum(az.x); az.y = wsum(az.y); az.z = wsum(az.z); az.w = wsum(az.w);
            an.x = wsum(an.x); an.y = wsum(an.y); an.z = wsum(an.z); an.w = wsum(an.w);

            int b = lane & 3;
            float xr = __shfl_sync(0xffffffffu, xiv, b);
            float xz = __shfl_sync(0xffffffffu, xiv, 4 + b);
            float xn = __shfl_sync(0xffffffffu, xiv, 8 + b);
            if (lane < 4) {
                float arb = (b & 1) ? ((b & 2) ? ar.w : ar.y) : ((b & 2) ? ar.z : ar.x);
                float azb = (b & 1) ? ((b & 2) ? az.w : az.y) : ((b & 2) ? az.z : az.x);
                float anb = (b & 1) ? ((b & 2) ? an.w : an.y) : ((b & 2) ? an.z : an.x);
                float4 hj = h_s[j];
                float hob = (b & 1) ? ((b & 2) ? hj.w : hj.y) : ((b & 2) ? hj.z : hj.x);
                float r = 1.f / (1.f + expf(-(xr + arb)));
                float z = 1.f / (1.f + expf(-(xz + azb)));
                float n = tanhf(xn + r * anb);
                float hv = (1.f - z) * n + z * hob;
                __stcg(hdst + b * GH_ + j, hv);
                g_hs[(size_t)(b * S_ + step) * GH_ + j] = hv;
            }
        }
    }
    target += nb; gsync(target);
    if (blockIdx.x == 0) {
        const float* hf = g_hbuf;   // 512 steps even -> buffer 0
        for (int i = t; i < B_ * GH_; i += 512) out_hn[i] = __ldcg(hf + i);
    }
}

// -------- per-token: normalize rout, gram penalty, cosine sims --------
__global__ void __launch_bounds__(128) token_kernel(const float* __restrict__ expr,
                                                    float* __restrict__ cosO) {
    const int token = blockIdx.x;
    const int t = threadIdx.x, lane = t & 31, warp = t >> 5;
    __shared__ float sv[16 * 132];
    __shared__ float gm[16][17];
    __shared__ float pen_s[16];
    const float* rout = g_hs + (size_t)token * GH_;

    for (int e = warp; e < 16; e += 4) {
        float s = 0.f;
        for (int d = lane; d < 128; d += 32) { float v = rout[e * 128 + d]; s += v * v; }
        s = wsum(s);
        float inv = 1.f / fmaxf(sqrtf(s), 1e-12f);
        for (int d = lane; d < 128; d += 32) sv[e * 132 + d] = rout[e * 128 + d] * inv;
    }
    __syncthreads();
    for (int p = t; p < 256; p += 128) {
        int e = p >> 4, f = p & 15;
        float s = 0.f;
#pragma unroll 8
        for (int k = 0; k < 128; k++) s += sv[e * 132 + k] * sv[f * 132 + k];
        gm[e][f] = s;
    }
    __syncthreads();
    if (t < 16) {
        float s2 = 0.f;
        for (int f = 0; f < 16; f++) {
            float d = gm[t][f] - (t == f ? 1.f : 0.f);
            s2 += d * d;
        }
        float nrm = fmaxf(sqrtf(s2), 1e-12f);
        pen_s[t] = s2 / (nrm * nrm);
    }
    __syncthreads();
    if (t == 0) {
        float s = 0.f;
        for (int e = 0; e < 16; e++) s += pen_s[e];
        g_pen[token] = s;
    }
    for (int e = warp; e < 16; e += 4) {
        float dot = 0.f, ss = 0.f, rs = 0.f;
        for (int d = lane; d < 128; d += 32) {
            float ev = expr[(size_t)token * GH_ + e * 128 + d];
            float rv = sv[e * 132 + d];
            dot += ev * rv; ss += ev * ev; rs += rv * rv;
        }
        dot = wsum(dot); ss = wsum(ss); rs = wsum(rs);
        if (lane == 0) {
            float en = fmaxf(sqrtf(ss), 1e-8f);
            float rn = fmaxf(sqrtf(rs), 1e-8f);
            cosO[token * 16 + e] = 1.f - dot / (en * rn);
        }
    }
}

// -------- penalty mean + load-balance adjustment --------
__global__ void finalize_kernel(const float* __restrict__ ema, float* __restrict__ out) {
    __shared__ float red[256];
    int t = threadIdx.x;
    float s = 0.f;
    for (int i = t; i < NTOK; i += 256) s += g_pen[i];
    red[t] = s; __syncthreads();
    for (int o = 128; o > 0; o >>= 1) { if (t < o) red[t] += red[t + o]; __syncthreads(); }
    if (t == 0) {
        float pen = red[0] / (float)NTOK;
        g_scal[0] = pen;
        out[O_PEN] = pen;
        float tot = 0.f;
        for (int e = 0; e < 16; e++) tot += ema[e];
        for (int e = 0; e < 16; e++) {
            float sc = (tot > 0.f) ? ema[e] / fmaxf(tot, 1e-12f) : 0.f;
            g_scal[1 + e] = sc * 0.01f * 16.f;
        }
    }
}

// -------- top-2 + softmax + adjustment --------
__global__ void topk_kernel(const float* __restrict__ cosv, float* __restrict__ out) {
    int token = blockIdx.x * blockDim.x + threadIdx.x;
    if (token >= NTOK) return;
    float mul = 1.f + g_scal[0];
    float dv[16];
#pragma unroll
    for (int e = 0; e < 16; e++) dv[e] = cosv[token * 16 + e] * mul;
    int i0 = 0; float v0 = dv[0];
#pragma unroll
    for (int e = 1; e < 16; e++) if (dv[e] > v0) { v0 = dv[e]; i0 = e; }
    int i1 = (i0 == 0) ? 1 : 0; float v1 = dv[i1];
#pragma unroll
    for (int e = 0; e < 16; e++) if (e != i0 && dv[e] > v1) { v1 = dv[e]; i1 = e; }
    float e1  = expf(v1 - v0);
    float inv = 1.f / (1.f + e1);
    out[O_MULT + token * 2 + 0] = inv - g_scal[1 + i0];
    out[O_MULT + token * 2 + 1] = e1 * inv - g_scal[1 + i1];
    out[O_SEL + token * 2 + 0] = (float)i0;
    out[O_SEL + token * 2 + 1] = (float)i1;
}

__global__ void wloss_reduce_kernel(float* __restrict__ out) {
    __shared__ float red[256];
    int t = threadIdx.x;
    float s = g_losspart[t];
    red[t] = s; __syncthreads();
    for (int o = 128; o > 0; o >>= 1) { if (t < o) red[t] += red[t + o]; __syncthreads(); }
    if (t == 0) out[O_LOSS] = red[0] / ((float)GH_ * (float)GH_);
}

// -------- host --------
extern "C" void kernel_launch(void* const* d_in, const int* in_sizes, int n_in,
                              void* d_out, int out_size) {
    const float* x      = (const float*)d_in[0];
    const float* hn     = (const float*)d_in[1];
    const float* w_ih   = (const float*)d_in[2];
    const float* w_hh   = (const float*)d_in[3];
    const float* w_expr = (const float*)d_in[4];
    const float* ema    = (const float*)d_in[5];
    float* out = (float*)d_out;

    void* p = 0;
    cudaGetSymbolAddress(&p, g_xi);
    float* xi = (float*)p;

    int sm = 0;
    cudaDeviceGetAttribute(&sm, cudaDevAttrMultiProcessorCount, 0);
    if (sm <= 0) sm = 132;

    init_kernel<<<32, 256>>>(hn);

    // xi = x @ w_ih^T   : A=x[M=2048,K=2048], B=w_ih[N=6144,K=2048] (OPB=1)
    sgemm2_kernel<0, 1, 0><<<dim3(G3_ / 128, NTOK / 128), 256>>>(x, w_ih, xi, NTOK, G3_, H_);

    // expr = x @ w_expr : B=w_expr[K=2048,N=2048] (OPB=0)
    sgemm2_kernel<0, 0, 0><<<dim3(GH_ / 128, NTOK / 128), 256>>>(x, w_expr, out + O_EXPR, NTOK, GH_, H_);

    gru_kernel<<<sm, 512>>>(w_hh, out + O_HN);

    token_kernel<<<NTOK, 128>>>(out + O_EXPR, out + O_COS);
    finalize_kernel<<<1, 256>>>(ema, out);
    topk_kernel<<<8, 256>>>(out + O_COS, out);

    // wloss: C = W^T W  : A=W[K=2048,M=2048] (OPA=1), B=W (OPB=0), EPI=1
    sgemm2_kernel<1, 0, 1><<<dim3(16, 16), 256>>>(w_expr, w_expr, nullptr, GH_, GH_, GH_);
    wloss_reduce_kernel<<<1, 256>>>(out);
}

// round 3
// speedup vs baseline: 2.0086x; 1.1317x over previous
#include <cuda_runtime.h>
#include <math.h>
#include <stdint.h>

// Problem dims
#define B_   4
#define S_   512
#define H_   2048
#define E_   16
#define D_   128
#define GH_  2048
#define G3_  6144
#define NTOK 2048   // B_*S_

// Output layout (flat f32 concat, reference return order)
#define O_MULT 0
#define O_SEL  4096
#define O_EXPR 8192
#define O_HN   4202496
#define O_PEN  4210688
#define O_COS  4210689
#define O_LOSS 4243457

// -------- device scratch --------
__device__ float    g_xi[NTOK * G3_];      // 50.3 MB
__device__ float    g_hs[NTOK * GH_];      // 16.8 MB
__device__ float    g_hbuf[2 * B_ * GH_];
__device__ float    g_pen[NTOK];
__device__ float    g_scal[32];
__device__ float    g_losspart[256];
__device__ unsigned g_ctr;

// -------- helpers --------
__device__ __forceinline__ float wsum(float v) {
#pragma unroll
    for (int o = 16; o > 0; o >>= 1) v += __shfl_xor_sync(0xffffffffu, v, o);
    return v;
}
__device__ __forceinline__ uint64_t pk2(float lo, float hi) {
    uint64_t r; asm("mov.b64 %0,{%1,%2};" : "=l"(r) : "f"(lo), "f"(hi)); return r;
}
__device__ __forceinline__ float2 upk2(uint64_t v) {
    float2 r; asm("mov.b64 {%0,%1}, %2;" : "=f"(r.x), "=f"(r.y) : "l"(v)); return r;
}
__device__ __forceinline__ void fma2(uint64_t& d, uint64_t a, uint64_t b) {
    asm("fma.rn.f32x2 %0, %1, %2, %3;" : "=l"(d) : "l"(a), "l"(b), "l"(d));
}
__device__ __forceinline__ void gsync(unsigned target) {
    __threadfence();
    __syncthreads();
    if (threadIdx.x == 0) {
        atomicAdd(&g_ctr, 1u);
        volatile unsigned* p = &g_ctr;
        while (*p < target) { __nanosleep(32); }
    }
    __syncthreads();
}

// -------- init --------
__global__ void init_kernel(const float* __restrict__ hn) {
    int i = blockIdx.x * 256 + threadIdx.x;
    if (i == 0) g_ctr = 0u;
    if (i < B_ * GH_) g_hbuf[i] = hn[i];
}

// ================= SGEMM: C[M,N] = opA(A) * opB(B) =================
// OPA==0: A[M,K] rm.  OPA==1: A[K,M] rm (A^T).  OPB==0: B[K,N].  OPB==1: B[N,K] (B^T).
// EPI==0 store C; EPI==1 reduce sum((C-I)^2) -> g_losspart.
// 128x128x16 tile, 256 thr, 8x8 microtile, double-buffered smem, fma.rn.f32x2.
template <int OPA, int OPB, int EPI>
__global__ void __launch_bounds__(256, 2) sgemm2_kernel(
    const float* __restrict__ A, const float* __restrict__ Bm,
    float* __restrict__ C, int M, int N, int K)
{
    __shared__ float As[2][16][128];
    __shared__ float Bs[2][16][128];
    const int m0 = blockIdx.y * 128;
    const int n0 = blockIdx.x * 128;
    const int t  = threadIdx.x;
    const int tx = t & 15;
    const int ty = t >> 4;

    uint64_t acc2[4][8];
#pragma unroll
    for (int p = 0; p < 4; p++)
#pragma unroll
        for (int j = 0; j < 8; j++) acc2[p][j] = 0ull;

    float4 pa[2], pb[2];

    auto loadA = [&](int k0, float4* r) {
        if (OPA == 0) {
            int m  = t & 127;
            int kq = t >> 7;
#pragma unroll
            for (int f = 0; f < 2; f++)
                r[f] = *reinterpret_cast<const float4*>(
                    &A[(size_t)(m0 + m) * K + k0 + (kq + 2 * f) * 4]);
        } else {
            int kk = t >> 5, m4 = t & 31;
#pragma unroll
            for (int f = 0; f < 2; f++)
                r[f] = *reinterpret_cast<const float4*>(
                    &A[(size_t)(k0 + kk + 8 * f) * M + m0 + m4 * 4]);
        }
    };
    auto loadB = [&](int k0, float4* r) {
        if (OPB == 0) {
            int kk = t >> 5, n4 = t & 31;
#pragma unroll
            for (int f = 0; f < 2; f++)
                r[f] = *reinterpret_cast<const float4*>(
                    &Bm[(size_t)(k0 + kk + 8 * f) * N + n0 + n4 * 4]);
        } else {
            int n  = t & 127;
            int kq = t >> 7;
#pragma unroll
            for (int f = 0; f < 2; f++)
                r[f] = *reinterpret_cast<const float4*>(
                    &Bm[(size_t)(n0 + n) * K + k0 + (kq + 2 * f) * 4]);
        }
    };
    auto storeA = [&](int b, const float4* r) {
        if (OPA == 0) {
            int m = t & 127, kq = t >> 7;
#pragma unroll
            for (int f = 0; f < 2; f++) {
                int ko = (kq + 2 * f) * 4;
                As[b][ko + 0][m] = r[f].x; As[b][ko + 1][m] = r[f].y;
                As[b][ko + 2][m] = r[f].z; As[b][ko + 3][m] = r[f].w;
            }
        } else {
            int kk = t >> 5, m4 = t & 31;
#pragma unroll
            for (int f = 0; f < 2; f++)
                *reinterpret_cast<float4*>(&As[b][kk + 8 * f][m4 * 4]) = r[f];
        }
    };
    auto storeB = [&](int b, const float4* r) {
        if (OPB == 0) {
            int kk = t >> 5, n4 = t & 31;
#pragma unroll
            for (int f = 0; f < 2; f++)
                *reinterpret_cast<float4*>(&Bs[b][kk + 8 * f][n4 * 4]) = r[f];
        } else {
            int n = t & 127, kq = t >> 7;
#pragma unroll
            for (int f = 0; f < 2; f++) {
                int ko = (kq + 2 * f) * 4;
                Bs[b][ko + 0][n] = r[f].x; Bs[b][ko + 1][n] = r[f].y;
                Bs[b][ko + 2][n] = r[f].z; Bs[b][ko + 3][n] = r[f].w;
            }
        }
    };

    const int KT = K >> 4;
    loadA(0, pa); loadB(0, pb);
    storeA(0, pa); storeB(0, pb);
    __syncthreads();
    int buf = 0;

    for (int kt = 0; kt < KT; kt++) {
        if (kt + 1 < KT) { loadA((kt + 1) << 4, pa); loadB((kt + 1) << 4, pb); }
#pragma unroll
        for (int k = 0; k < 16; k++) {
            ulonglong2 a0 = *reinterpret_cast<const ulonglong2*>(&As[buf][k][ty * 4]);
            ulonglong2 a1 = *reinterpret_cast<const ulonglong2*>(&As[buf][k][64 + ty * 4]);
            float4 b0 = *reinterpret_cast<const float4*>(&Bs[buf][k][tx * 4]);
            float4 b1 = *reinterpret_cast<const float4*>(&Bs[buf][k][64 + tx * 4]);
            uint64_t av[4] = { a0.x, a0.y, a1.x, a1.y };
            uint64_t bd[8] = { pk2(b0.x, b0.x), pk2(b0.y, b0.y), pk2(b0.z, b0.z), pk2(b0.w, b0.w),
                               pk2(b1.x, b1.x), pk2(b1.y, b1.y), pk2(b1.z, b1.z), pk2(b1.w, b1.w) };
#pragma unroll
            for (int p = 0; p < 4; p++)
#pragma unroll
                for (int j = 0; j < 8; j++) fma2(acc2[p][j], av[p], bd[j]);
        }
        if (kt + 1 < KT) {
            storeA(buf ^ 1, pa); storeB(buf ^ 1, pb);
            __syncthreads();
            buf ^= 1;
        }
    }

    // acc2[p][j]: p -> m pair base: p<2 ? ty*4+2p : 64+ty*4+2(p-2); (.x,.y)=(m,m+1)
    //             j -> n: j<4 ? tx*4+j : 64+tx*4+(j-4)
    if (EPI == 0) {
#pragma unroll
        for (int p = 0; p < 4; p++) {
            int mb = m0 + ((p < 2) ? (ty * 4 + 2 * p) : (64 + ty * 4 + 2 * (p - 2)));
            float2 c[8];
#pragma unroll
            for (int j = 0; j < 8; j++) c[j] = upk2(acc2[p][j]);
            *reinterpret_cast<float4*>(&C[(size_t)mb * N + n0 + tx * 4]) =
                make_float4(c[0].x, c[1].x, c[2].x, c[3].x);
            *reinterpret_cast<float4*>(&C[(size_t)mb * N + n0 + 64 + tx * 4]) =
                make_float4(c[4].x, c[5].x, c[6].x, c[7].x);
            *reinterpret_cast<float4*>(&C[(size_t)(mb + 1) * N + n0 + tx * 4]) =
                make_float4(c[0].y, c[1].y, c[2].y, c[3].y);
            *reinterpret_cast<float4*>(&C[(size_t)(mb + 1) * N + n0 + 64 + tx * 4]) =
                make_float4(c[4].y, c[5].y, c[6].y, c[7].y);
        }
    } else {
        float s = 0.f;
#pragma unroll
        for (int p = 0; p < 4; p++) {
            int mb = m0 + ((p < 2) ? (ty * 4 + 2 * p) : (64 + ty * 4 + 2 * (p - 2)));
#pragma unroll
            for (int j = 0; j < 8; j++) {
                float2 c = upk2(acc2[p][j]);
                int gj = n0 + ((j < 4) ? (tx * 4 + j) : (64 + tx * 4 + (j - 4)));
                float d0 = c.x - (mb == gj ? 1.f : 0.f);
                float d1 = c.y - (mb + 1 == gj ? 1.f : 0.f);
                s += d0 * d0 + d1 * d1;
            }
        }
        __shared__ float red[256];
        red[t] = s; __syncthreads();
        for (int o = 128; o > 0; o >>= 1) { if (t < o) red[t] += red[t + o]; __syncthreads(); }
        if (t == 0) g_losspart[blockIdx.y * gridDim.x + blockIdx.x] = red[0];
    }
}

// ================= persistent GRU, 1024 thr, split-K=2 =================
__global__ void __launch_bounds__(1024) gru_kernel(const float* __restrict__ w_hh,
                                                   float* __restrict__ out_hn) {
    __shared__ float4 h_s[GH_];
    __shared__ float part[16][12];
    const int t    = threadIdx.x;
    const int lane = t & 31;
    const int warp = t >> 5;           // 0..31
    const int pair = warp >> 1;        // 0..15
    const int half = warp & 1;
    const int nb   = gridDim.x;
    const int j    = pair * 152 + blockIdx.x;   // strided column map
    const bool valid = (j < GH_);
    unsigned target = 0;

    for (int step = 0; step < S_; step++) {
        if (step > 0) { target += nb; gsync(target); }
        const float* hsrc = g_hbuf + (step & 1) * (B_ * GH_);
        for (int k = t; k < GH_; k += 1024) {
            h_s[k] = make_float4(__ldcg(hsrc + k),
                                 __ldcg(hsrc + GH_ + k),
                                 __ldcg(hsrc + 2 * GH_ + k),
                                 __ldcg(hsrc + 3 * GH_ + k));
        }
        __syncthreads();
        float* hdst = g_hbuf + ((step + 1) & 1) * (B_ * GH_);

        float4 ar = make_float4(0.f, 0.f, 0.f, 0.f);
        float4 az = ar, an = ar;
        float xiv = 0.f;
        if (valid) {
            if (half == 0 && lane < 12)
                xiv = g_xi[(size_t)((lane & 3) * S_ + step) * G3_ + (lane >> 2) * GH_ + j];
            const float* wr = w_hh + (size_t)j * GH_;
            const float* wz = w_hh + (size_t)(GH_ + j) * GH_;
            const float* wn = w_hh + (size_t)(2 * GH_ + j) * GH_;
            const int kend = half * 1024 + 1024;
            for (int k = half * 1024 + lane * 4; k < kend; k += 128) {
                float4 r4 = *reinterpret_cast<const float4*>(wr + k);
                float4 z4 = *reinterpret_cast<const float4*>(wz + k);
                float4 n4 = *reinterpret_cast<const float4*>(wn + k);
                float4 h0 = h_s[k], h1 = h_s[k + 1], h2 = h_s[k + 2], h3 = h_s[k + 3];
                ar.x += r4.x*h0.x + r4.y*h1.x + r4.z*h2.x + r4.w*h3.x;
                ar.y += r4.x*h0.y + r4.y*h1.y + r4.z*h2.y + r4.w*h3.y;
                ar.z += r4.x*h0.z + r4.y*h1.z + r4.z*h2.z + r4.w*h3.z;
                ar.w += r4.x*h0.w + r4.y*h1.w + r4.z*h2.w + r4.w*h3.w;
                az.x += z4.x*h0.x + z4.y*h1.x + z4.z*h2.x + z4.w*h3.x;
                az.y += z4.x*h0.y + z4.y*h1.y + z4.z*h2.y + z4.w*h3.y;
                az.z += z4.x*h0.z + z4.y*h1.z + z4.z*h2.z + z4.w*h3.z;
                az.w += z4.x*h0.w + z4.y*h1.w + z4.z*h2.w + z4.w*h3.w;
                an.x += n4.x*h0.x + n4.y*h1.x + n4.z*h2.x + n4.w*h3.x;
                an.y += n4.x*h0.y + n4.y*h1.y + n4.z*h2.y + n4.w*h3.y;
                an.z += n4.x*h0.z + n4.y*h1.z + n4.z*h2.z + n4.w*h3.z;
                an.w += n4.x*h0.w + n4.y*h1.w + n4.z*h2.w + n4.w*h3.w;
            }
            ar.x = wsum(ar.x); ar.y = wsum(ar.y); ar.z = wsum(ar.z); ar.w = wsum(ar.w);
            az.x = wsum(az.x); az.y = wsum(az.y); az.z = wsum(az.z); az.w = wsum(az.w);
            an.x = wsum(an.x); an.y = wsum(an.y); an.z = wsum(an.z); an.w = wsum(an.w);
            if (half == 1 && lane == 0) {
                part[pair][0]  = ar.x; part[pair][1]  = ar.y;
                part[pair][2]  = ar.z; part[pair][3]  = ar.w;
                part[pair][4]  = az.x; part[pair][5]  = az.y;
                part[pair][6]  = az.z; part[pair][7]  = az.w;
                part[pair][8]  = an.x; part[pair][9]  = an.y;
                part[pair][10] = an.z; part[pair][11] = an.w;
            }
        }
        __syncthreads();
        if (valid && half == 0) {
            int b = lane & 3;
            float xr = __shfl_sync(0xffffffffu, xiv, b);
            float xz = __shfl_sync(0xffffffffu, xiv, 4 + b);
            float xn = __shfl_sync(0xffffffffu, xiv, 8 + b);
            if (lane < 4) {
                float arb = ((b & 1) ? ((b & 2) ? ar.w : ar.y) : ((b & 2) ? ar.z : ar.x))
                            + part[pair][b];
                float azb = ((b & 1) ? ((b & 2) ? az.w : az.y) : ((b & 2) ? az.z : az.x))
                            + part[pair][4 + b];
                float anb = ((b & 1) ? ((b & 2) ? an.w : an.y) : ((b & 2) ? an.z : an.x))
                            + part[pair][8 + b];
                float4 hj = h_s[j];
                float hob = (b & 1) ? ((b & 2) ? hj.w : hj.y) : ((b & 2) ? hj.z : hj.x);
                float r = 1.f / (1.f + expf(-(xr + arb)));
                float z = 1.f / (1.f + expf(-(xz + azb)));
                float n = tanhf(xn + r * anb);
                float hv = (1.f - z) * n + z * hob;
                __stcg(hdst + b * GH_ + j, hv);
                g_hs[(size_t)(b * S_ + step) * GH_ + j] = hv;
            }
        }
    }
    target += nb; gsync(target);
    if (blockIdx.x == 0) {
        const float* hf = g_hbuf;   // 512 steps even -> buffer 0
        for (int i = t; i < B_ * GH_; i += 1024) out_hn[i] = __ldcg(hf + i);
    }
}

// -------- per-token: normalize rout, gram penalty, cosine sims --------
__global__ void __launch_bounds__(128) token_kernel(const float* __restrict__ expr,
                                                    float* __restrict__ cosO) {
    const int token = blockIdx.x;
    const int t = threadIdx.x, lane = t & 31, warp = t >> 5;
    __shared__ float sv[16 * 132];
    __shared__ float gm[16][17];
    __shared__ float pen_s[16];
    const float* rout = g_hs + (size_t)token * GH_;

    for (int e = warp; e < 16; e += 4) {
        float s = 0.f;
        for (int d = lane; d < 128; d += 32) { float v = rout[e * 128 + d]; s += v * v; }
        s = wsum(s);
        float inv = 1.f / fmaxf(sqrtf(s), 1e-12f);
        for (int d = lane; d < 128; d += 32) sv[e * 132 + d] = rout[e * 128 + d] * inv;
    }
    __syncthreads();
    for (int p = t; p < 256; p += 128) {
        int e = p >> 4, f = p & 15;
        float s = 0.f;
#pragma unroll 8
        for (int k = 0; k < 128; k++) s += sv[e * 132 + k] * sv[f * 132 + k];
        gm[e][f] = s;
    }
    __syncthreads();
    if (t < 16) {
        float s2 = 0.f;
        for (int f = 0; f < 16; f++) {
            float d = gm[t][f] - (t == f ? 1.f : 0.f);
            s2 += d * d;
        }
        float nrm = fmaxf(sqrtf(s2), 1e-12f);
        pen_s[t] = s2 / (nrm * nrm);
    }
    __syncthreads();
    if (t == 0) {
        float s = 0.f;
        for (int e = 0; e < 16; e++) s += pen_s[e];
        g_pen[token] = s;
    }
    for (int e = warp; e < 16; e += 4) {
        float dot = 0.f, ss = 0.f, rs = 0.f;
        for (int d = lane; d < 128; d += 32) {
            float ev = expr[(size_t)token * GH_ + e * 128 + d];
            float rv = sv[e * 132 + d];
            dot += ev * rv; ss += ev * ev; rs += rv * rv;
        }
        dot = wsum(dot); ss = wsum(ss); rs = wsum(rs);
        if (lane == 0) {
            float en = fmaxf(sqrtf(ss), 1e-8f);
            float rn = fmaxf(sqrtf(rs), 1e-8f);
            cosO[token * 16 + e] = 1.f - dot / (en * rn);
        }
    }
}

// -------- penalty mean + load-balance adjustment --------
__global__ void finalize_kernel(const float* __restrict__ ema, float* __restrict__ out) {
    __shared__ float red[256];
    int t = threadIdx.x;
    float s = 0.f;
    for (int i = t; i < NTOK; i += 256) s += g_pen[i];
    red[t] = s; __syncthreads();
    for (int o = 128; o > 0; o >>= 1) { if (t < o) red[t] += red[t + o]; __syncthreads(); }
    if (t == 0) {
        float pen = red[0] / (float)NTOK;
        g_scal[0] = pen;
        out[O_PEN] = pen;
        float tot = 0.f;
        for (int e = 0; e < 16; e++) tot += ema[e];
        for (int e = 0; e < 16; e++) {
            float sc = (tot > 0.f) ? ema[e] / fmaxf(tot, 1e-12f) : 0.f;
            g_scal[1 + e] = sc * 0.01f * 16.f;
        }
    }
}

// -------- top-2 + softmax + adjustment --------
__global__ void topk_kernel(const float* __restrict__ cosv, float* __restrict__ out) {
    int token = blockIdx.x * blockDim.x + threadIdx.x;
    if (token >= NTOK) return;
    float mul = 1.f + g_scal[0];
    float dv[16];
#pragma unroll
    for (int e = 0; e < 16; e++) dv[e] = cosv[token * 16 + e] * mul;
    int i0 = 0; float v0 = dv[0];
#pragma unroll
    for (int e = 1; e < 16; e++) if (dv[e] > v0) { v0 = dv[e]; i0 = e; }
    int i1 = (i0 == 0) ? 1 : 0; float v1 = dv[i1];
#pragma unroll
    for (int e = 0; e < 16; e++) if (e != i0 && dv[e] > v1) { v1 = dv[e]; i1 = e; }
    float e1  = expf(v1 - v0);
    float inv = 1.f / (1.f + e1);
    out[O_MULT + token * 2 + 0] = inv - g_scal[1 + i0];
    out[O_MULT + token * 2 + 1] = e1 * inv - g_scal[1 + i1];
    out[O_SEL + token * 2 + 0] = (float)i0;
    out[O_SEL + token * 2 + 1] = (float)i1;
}

__global__ void wloss_reduce_kernel(float* __restrict__ out) {
    __shared__ float red[256];
    int t = threadIdx.x;
    float s = g_losspart[t];
    red[t] = s; __syncthreads();
    for (int o = 128; o > 0; o >>= 1) { if (t < o) red[t] += red[t + o]; __syncthreads(); }
    if (t == 0) out[O_LOSS] = red[0] / ((float)GH_ * (float)GH_);
}

// -------- host --------
extern "C" void kernel_launch(void* const* d_in, const int* in_sizes, int n_in,
                              void* d_out, int out_size) {
    const float* x      = (const float*)d_in[0];
    const float* hn     = (const float*)d_in[1];
    const float* w_ih   = (const float*)d_in[2];
    const float* w_hh   = (const float*)d_in[3];
    const float* w_expr = (const float*)d_in[4];
    const float* ema    = (const float*)d_in[5];
    float* out = (float*)d_out;

    void* p = 0;
    cudaGetSymbolAddress(&p, g_xi);
    float* xi = (float*)p;

    int sm = 0;
    cudaDeviceGetAttribute(&sm, cudaDevAttrMultiProcessorCount, 0);
    if (sm <= 0) sm = 152;

    init_kernel<<<32, 256>>>(hn);

    // xi = x @ w_ih^T
    sgemm2_kernel<0, 1, 0><<<dim3(G3_ / 128, NTOK / 128), 256>>>(x, w_ih, xi, NTOK, G3_, H_);
    // expr = x @ w_expr
    sgemm2_kernel<0, 0, 0><<<dim3(GH_ / 128, NTOK / 128), 256>>>(x, w_expr, out + O_EXPR, NTOK, GH_, H_);

    gru_kernel<<<152, 1024>>>(w_hh, out + O_HN);

    token_kernel<<<NTOK, 128>>>(out + O_EXPR, out + O_COS);
    finalize_kernel<<<1, 256>>>(ema, out);
    topk_kernel<<<8, 256>>>(out + O_COS, out);

    // wloss: C = W^T W
    sgemm2_kernel<1, 0, 1><<<dim3(16, 16), 256>>>(w_expr, w_expr, nullptr, GH_, GH_, GH_);
    wloss_reduce_kernel<<<1, 256>>>(out);
}

// round 5
// speedup vs baseline: 2.2443x; 1.1174x over previous
#include <cuda_runtime.h>
#include <cuda_bf16.h>
#include <math.h>
#include <stdint.h>

// Problem dims
#define B_   4
#define S_   512
#define H_   2048
#define E_   16
#define D_   128
#define GH_  2048
#define G3_  6144
#define NTOK 2048   // B_*S_

// Output layout (flat f32 concat, reference return order)
#define O_MULT 0
#define O_SEL  4096
#define O_EXPR 8192
#define O_HN   4202496
#define O_PEN  4210688
#define O_COS  4210689
#define O_LOSS 4243457

// -------- device scratch --------
__device__ float    g_xi[NTOK * G3_];      // 50.3 MB
__device__ float    g_hs[NTOK * GH_];      // 16.8 MB
__device__ float    g_hbuf[2 * B_ * GH_];
__device__ float    g_pen[NTOK];
__device__ float    g_scal[32];
__device__ float    g_losspart[1024];
__device__ unsigned g_ctr;

// bf16 hi/lo split operands (16B aligned for uint4 access)
__device__ __align__(16) __nv_bfloat16 g_xh[NTOK * H_];
__device__ __align__(16) __nv_bfloat16 g_xl[NTOK * H_];
__device__ __align__(16) __nv_bfloat16 g_wih_h[G3_ * H_];
__device__ __align__(16) __nv_bfloat16 g_wih_l[G3_ * H_];
__device__ __align__(16) __nv_bfloat16 g_weT_h[GH_ * H_];
__device__ __align__(16) __nv_bfloat16 g_weT_l[GH_ * H_];

// -------- helpers --------
__device__ __forceinline__ float wsum(float v) {
#pragma unroll
    for (int o = 16; o > 0; o >>= 1) v += __shfl_xor_sync(0xffffffffu, v, o);
    return v;
}
__device__ __forceinline__ void gsync(unsigned target) {
    __threadfence();
    __syncthreads();
    if (threadIdx.x == 0) {
        atomicAdd(&g_ctr, 1u);
        volatile unsigned* p = &g_ctr;
        while (*p < target) { __nanosleep(32); }
    }
    __syncthreads();
}
__device__ __forceinline__ uint32_t smem_u32(const void* p) {
    uint32_t a;
    asm("{ .reg .u64 t; cvta.to.shared.u64 t, %1; cvt.u32.u64 %0, t; }"
        : "=r"(a) : "l"(p));
    return a;
}
__device__ __forceinline__ void ldsm4(uint32_t addr, uint32_t* r) {
    asm volatile("ldmatrix.sync.aligned.m8n8.x4.shared.b16 {%0,%1,%2,%3}, [%4];"
                 : "=r"(r[0]), "=r"(r[1]), "=r"(r[2]), "=r"(r[3]) : "r"(addr));
}
__device__ __forceinline__ void mma16816(float* c, const uint32_t* a,
                                         uint32_t b0, uint32_t b1) {
    asm volatile(
        "mma.sync.aligned.m16n8k16.row.col.f32.bf16.bf16.f32 "
        "{%0,%1,%2,%3}, {%4,%5,%6,%7}, {%8,%9}, {%0,%1,%2,%3};"
        : "+f"(c[0]), "+f"(c[1]), "+f"(c[2]), "+f"(c[3])
        : "r"(a[0]), "r"(a[1]), "r"(a[2]), "r"(a[3]), "r"(b0), "r"(b1));
}

// -------- init --------
__global__ void init_kernel(const float* __restrict__ hn) {
    int i = blockIdx.x * 256 + threadIdx.x;
    if (i == 0) g_ctr = 0u;
    if (i < B_ * GH_) g_hbuf[i] = hn[i];
}

// -------- split f32 -> bf16 hi/lo --------
__global__ void split_kernel(const float* __restrict__ src,
                             __nv_bfloat16* __restrict__ hi,
                             __nv_bfloat16* __restrict__ lo, int n4) {
    int i = blockIdx.x * 256 + threadIdx.x;
    if (i >= n4) return;
    float4 v = reinterpret_cast<const float4*>(src)[i];
    __nv_bfloat16 h0 = __float2bfloat16(v.x), h1 = __float2bfloat16(v.y);
    __nv_bfloat16 h2 = __float2bfloat16(v.z), h3 = __float2bfloat16(v.w);
    __nv_bfloat16 l0 = __float2bfloat16(v.x - __bfloat162float(h0));
    __nv_bfloat16 l1 = __float2bfloat16(v.y - __bfloat162float(h1));
    __nv_bfloat16 l2 = __float2bfloat16(v.z - __bfloat162float(h2));
    __nv_bfloat16 l3 = __float2bfloat16(v.w - __bfloat162float(h3));
    reinterpret_cast<__nv_bfloat162*>(hi)[2 * i]     = __nv_bfloat162(h0, h1);
    reinterpret_cast<__nv_bfloat162*>(hi)[2 * i + 1] = __nv_bfloat162(h2, h3);
    reinterpret_cast<__nv_bfloat162*>(lo)[2 * i]     = __nv_bfloat162(l0, l1);
    reinterpret_cast<__nv_bfloat162*>(lo)[2 * i + 1] = __nv_bfloat162(l2, l3);
}

// -------- transpose + split: W[H,GH] -> T[GH,H] bf16 hi/lo --------
__global__ void tsplit_kernel(const float* __restrict__ W,
                              __nv_bfloat16* __restrict__ Th,
                              __nv_bfloat16* __restrict__ Tl) {
    __shared__ float t[32][33];
    int gc = blockIdx.x * 32;   // GH base
    int gr = blockIdx.y * 32;   // H base
    int tx = threadIdx.x, ty = threadIdx.y;   // 32 x 8
#pragma unroll
    for (int r = 0; r < 32; r += 8)
        t[ty + r][tx] = W[(size_t)(gr + ty + r) * GH_ + gc + tx];
    __syncthreads();
#pragma unroll
    for (int r = 0; r < 32; r += 8) {
        float v = t[tx][ty + r];
        __nv_bfloat16 h = __float2bfloat16(v);
        __nv_bfloat16 l = __float2bfloat16(v - __bfloat162float(h));
        size_t o = (size_t)(gc + ty + r) * H_ + gr + tx;
        Th[o] = h; Tl[o] = l;
    }
}

// ========== mma.sync GEMM: C[M,N] = A @ B^T, bf16 hi/lo 3-term split =====
// A*: [M,K] bf16 row-major. B*: [N,K] bf16 row-major. K mult of 32.
// CTA tile 128x128, 8 warps (4x2), warp tile 32x64, K chunk 32, dbuf smem.
// EPI==0: store C. EPI==1: sum((C-I)^2) -> g_losspart.
#define ROWB  80                 // padded row stride bytes (64B data + 16B pad)
#define TILEB (128 * ROWB)       // 10240 bytes per operand tile
#define BUFB  (4 * TILEB)        // 40960 per stage
#define SMTOT (2 * BUFB)         // 81920

template <int EPI>
__global__ void __launch_bounds__(256) mma_gemm_kernel(
    const __nv_bfloat16* __restrict__ Ah, const __nv_bfloat16* __restrict__ Al,
    const __nv_bfloat16* __restrict__ Bh, const __nv_bfloat16* __restrict__ Bl,
    float* __restrict__ C, int N, int K)
{
    extern __shared__ char smem[];
    const uint32_t sb = smem_u32(smem);
    const int t    = threadIdx.x;
    const int lane = t & 31;
    const int w    = t >> 5;
    const int wm   = w >> 1;      // 0..3
    const int wn   = w & 1;       // 0..1
    const int n0   = blockIdx.x * 128;
    const int m0   = blockIdx.y * 128;

    const __nv_bfloat16* srcs[4] = {
        Ah + (size_t)m0 * K, Al + (size_t)m0 * K,
        Bh + (size_t)n0 * K, Bl + (size_t)n0 * K };

    // per-thread staging coords: 2 uint4 per tile, 4 tiles
    const int srow0 = t >> 2;            // f=0 rows 0..63
    const int srow1 = (t + 256) >> 2;    // f=1 rows 64..127
    const int sc16  = t & 3;

    float acc[2][8][4];
#pragma unroll
    for (int i = 0; i < 2; i++)
#pragma unroll
        for (int j = 0; j < 8; j++)
#pragma unroll
            for (int c = 0; c < 4; c++) acc[i][j][c] = 0.f;

    // ldmatrix source addresses (within a buffer), precomputed per thread
    // A: row = wm*32 + mt*16 + (lane&15), c16sub = lane>>4
    const uint32_t a_row  = wm * 32 + (lane & 15);
    const uint32_t a_cs   = lane >> 4;
    // B: nrow = wn*64 + ntp*16 + ((lane>>4)<<3) + (lane&7), c16sub = (lane>>3)&1
    const uint32_t b_row  = wn * 64 + ((lane >> 4) << 3) + (lane & 7);
    const uint32_t b_cs   = (lane >> 3) & 1;

    uint4 pf[8];
    const int NCH = K >> 5;   // K/32

    // prefetch chunk 0
#pragma unroll
    for (int o = 0; o < 4; o++) {
        pf[o * 2 + 0] = reinterpret_cast<const uint4*>(srcs[o] + (size_t)srow0 * K)[sc16];
        pf[o * 2 + 1] = reinterpret_cast<const uint4*>(srcs[o] + (size_t)srow1 * K)[sc16];
    }

    for (int ch = 0; ch < NCH; ch++) {
        const int buf = ch & 1;
        const uint32_t bb = buf * BUFB;
        // store staged chunk
#pragma unroll
        for (int o = 0; o < 4; o++) {
            *reinterpret_cast<uint4*>(smem + bb + o * TILEB + srow0 * ROWB + sc16 * 16) = pf[o * 2 + 0];
            *reinterpret_cast<uint4*>(smem + bb + o * TILEB + srow1 * ROWB + sc16 * 16) = pf[o * 2 + 1];
        }
        __syncthreads();
        // prefetch next chunk
        if (ch + 1 < NCH) {
            const int koff = (ch + 1) * 32;
#pragma unroll
            for (int o = 0; o < 4; o++) {
                pf[o * 2 + 0] = reinterpret_cast<const uint4*>(srcs[o] + (size_t)srow0 * K + koff)[sc16];
                pf[o * 2 + 1] = reinterpret_cast<const uint4*>(srcs[o] + (size_t)srow1 * K + koff)[sc16];
            }
        }
        // compute on buf
#pragma unroll
        for (int kt = 0; kt < 2; kt++) {
            uint32_t ah[2][4], al[2][4];
#pragma unroll
            for (int mt = 0; mt < 2; mt++) {
                uint32_t row = a_row + mt * 16;
                uint32_t off = bb + row * ROWB + (kt * 2 + a_cs) * 16;
                ldsm4(sb + off, ah[mt]);
                ldsm4(sb + TILEB + off, al[mt]);
            }
#pragma unroll
            for (int ntp = 0; ntp < 4; ntp++) {
                uint32_t nrow = b_row + ntp * 16;
                uint32_t off  = bb + 2 * TILEB + nrow * ROWB + (kt * 2 + b_cs) * 16;
                uint32_t bh[4], bl[4];
                ldsm4(sb + off, bh);
                ldsm4(sb + TILEB + off, bl);
#pragma unroll
                for (int mt = 0; mt < 2; mt++) {
                    mma16816(acc[mt][2 * ntp],     ah[mt], bh[0], bh[1]);
                    mma16816(acc[mt][2 * ntp],     ah[mt], bl[0], bl[1]);
                    mma16816(acc[mt][2 * ntp],     al[mt], bh[0], bh[1]);
                    mma16816(acc[mt][2 * ntp + 1], ah[mt], bh[2], bh[3]);
                    mma16816(acc[mt][2 * ntp + 1], ah[mt], bl[2], bl[3]);
                    mma16816(acc[mt][2 * ntp + 1], al[mt], bh[2], bh[3]);
                }
            }
        }
        __syncthreads();
    }

    // epilogue: fragment (mt,nt): rows m0+wm*32+mt*16+{g,g+8}, col n0+wn*64+nt*8+t2*2
    const int g  = lane >> 2;
    const int t2 = lane & 3;
    if (EPI == 0) {
#pragma unroll
        for (int mt = 0; mt < 2; mt++) {
            int row = m0 + wm * 32 + mt * 16 + g;
#pragma unroll
            for (int nt = 0; nt < 8; nt++) {
                int col = n0 + wn * 64 + nt * 8 + t2 * 2;
                *reinterpret_cast<float2*>(&C[(size_t)row * N + col]) =
                    make_float2(acc[mt][nt][0], acc[mt][nt][1]);
                *reinterpret_cast<float2*>(&C[(size_t)(row + 8) * N + col]) =
                    make_float2(acc[mt][nt][2], acc[mt][nt][3]);
            }
        }
    } else {
        float s = 0.f;
#pragma unroll
        for (int mt = 0; mt < 2; mt++) {
            int row = m0 + wm * 32 + mt * 16 + g;
#pragma unroll
            for (int nt = 0; nt < 8; nt++) {
                int col = n0 + wn * 64 + nt * 8 + t2 * 2;
                float d0 = acc[mt][nt][0] - (row == col ? 1.f : 0.f);
                float d1 = acc[mt][nt][1] - (row == col + 1 ? 1.f : 0.f);
                float d2 = acc[mt][nt][2] - (row + 8 == col ? 1.f : 0.f);
                float d3 = acc[mt][nt][3] - (row + 8 == col + 1 ? 1.f : 0.f);
                s += d0 * d0 + d1 * d1 + d2 * d2 + d3 * d3;
            }
        }
        float* red = reinterpret_cast<float*>(smem);
        red[t] = s; __syncthreads();
        for (int o = 128; o > 0; o >>= 1) { if (t < o) red[t] += red[t + o]; __syncthreads(); }
        if (t == 0) g_losspart[blockIdx.y * gridDim.x + blockIdx.x] = red[0];
    }
}

// ================= persistent GRU, 1024 thr, split-K=2 (unchanged R3) ====
__global__ void __launch_bounds__(1024) gru_kernel(const float* __restrict__ w_hh,
                                                   float* __restrict__ out_hn) {
    __shared__ float4 h_s[GH_];
    __shared__ float part[16][12];
    const int t    = threadIdx.x;
    const int lane = t & 31;
    const int warp = t >> 5;
    const int pair = warp >> 1;
    const int half = warp & 1;
    const int nb   = gridDim.x;
    const int j    = pair * 152 + blockIdx.x;
    const bool valid = (j < GH_);
    unsigned target = 0;

    for (int step = 0; step < S_; step++) {
        if (step > 0) { target += nb; gsync(target); }
        const float* hsrc = g_hbuf + (step & 1) * (B_ * GH_);
        for (int k = t; k < GH_; k += 1024) {
            h_s[k] = make_float4(__ldcg(hsrc + k),
                                 __ldcg(hsrc + GH_ + k),
                                 __ldcg(hsrc + 2 * GH_ + k),
                                 __ldcg(hsrc + 3 * GH_ + k));
        }
        __syncthreads();
        float* hdst = g_hbuf + ((step + 1) & 1) * (B_ * GH_);

        float4 ar = make_float4(0.f, 0.f, 0.f, 0.f);
        float4 az = ar, an = ar;
        float xiv = 0.f;
        if (valid) {
            if (half == 0 && lane < 12)
                xiv = g_xi[(size_t)((lane & 3) * S_ + step) * G3_ + (lane >> 2) * GH_ + j];
            const float* wr = w_hh + (size_t)j * GH_;
            const float* wz = w_hh + (size_t)(GH_ + j) * GH_;
            const float* wn = w_hh + (size_t)(2 * GH_ + j) * GH_;
            const int kend = half * 1024 + 1024;
            for (int k = half * 1024 + lane * 4; k < kend; k += 128) {
                float4 r4 = *reinterpret_cast<const float4*>(wr + k);
                float4 z4 = *reinterpret_cast<const float4*>(wz + k);
                float4 n4 = *reinterpret_cast<const float4*>(wn + k);
                float4 h0 = h_s[k], h1 = h_s[k + 1], h2 = h_s[k + 2], h3 = h_s[k + 3];
                ar.x += r4.x*h0.x + r4.y*h1.x + r4.z*h2.x + r4.w*h3.x;
                ar.y += r4.x*h0.y + r4.y*h1.y + r4.z*h2.y + r4.w*h3.y;
                ar.z += r4.x*h0.z + r4.y*h1.z + r4.z*h2.z + r4.w*h3.z;
                ar.w += r4.x*h0.w + r4.y*h1.w + r4.z*h2.w + r4.w*h3.w;
                az.x += z4.x*h0.x + z4.y*h1.x + z4.z*h2.x + z4.w*h3.x;
                az.y += z4.x*h0.y + z4.y*h1.y + z4.z*h2.y + z4.w*h3.y;
                az.z += z4.x*h0.z + z4.y*h1.z + z4.z*h2.z + z4.w*h3.z;
                az.w += z4.x*h0.w + z4.y*h1.w + z4.z*h2.w + z4.w*h3.w;
                an.x += n4.x*h0.x + n4.y*h1.x + n4.z*h2.x + n4.w*h3.x;
                an.y += n4.x*h0.y + n4.y*h1.y + n4.z*h2.y + n4.w*h3.y;
                an.z += n4.x*h0.z + n4.y*h1.z + n4.z*h2.z + n4.w*h3.z;
                an.w += n4.x*h0.w + n4.y*h1.w + n4.z*h2.w + n4.w*h3.w;
            }
            ar.x = wsum(ar.x); ar.y = wsum(ar.y); ar.z = wsum(ar.z); ar.w = wsum(ar.w);
            az.x = wsum(az.x); az.y = wsum(az.y); az.z = wsum(az.z); az.w = wsum(az.w);
            an.x = wsum(an.x); an.y = wsum(an.y); an.z = wsum(an.z); an.w = wsum(an.w);
            if (half == 1 && lane == 0) {
                part[pair][0]  = ar.x; part[pair][1]  = ar.y;
                part[pair][2]  = ar.z; part[pair][3]  = ar.w;
                part[pair][4]  = az.x; part[pair][5]  = az.y;
                part[pair][6]  = az.z; part[pair][7]  = az.w;
                part[pair][8]  = an.x; part[pair][9]  = an.y;
                part[pair][10] = an.z; part[pair][11] = an.w;
            }
        }
        __syncthreads();
        if (valid && half == 0) {
            int b = lane & 3;
            float xr = __shfl_sync(0xffffffffu, xiv, b);
            float xz = __shfl_sync(0xffffffffu, xiv, 4 + b);
            float xn = __shfl_sync(0xffffffffu, xiv, 8 + b);
            if (lane < 4) {
                float arb = ((b & 1) ? ((b & 2) ? ar.w : ar.y) : ((b & 2) ? ar.z : ar.x))
                            + part[pair][b];
                float azb = ((b & 1) ? ((b & 2) ? az.w : az.y) : ((b & 2) ? az.z : az.x))
                            + part[pair][4 + b];
                float anb = ((b & 1) ? ((b & 2) ? an.w : an.y) : ((b & 2) ? an.z : an.x))
                            + part[pair][8 + b];
                float4 hj = h_s[j];
                float hob = (b & 1) ? ((b & 2) ? hj.w : hj.y) : ((b & 2) ? hj.z : hj.x);
                float r = 1.f / (1.f + expf(-(xr + arb)));
                float z = 1.f / (1.f + expf(-(xz + azb)));
                float n = tanhf(xn + r * anb);
                float hv = (1.f - z) * n + z * hob;
                __stcg(hdst + b * GH_ + j, hv);
                g_hs[(size_t)(b * S_ + step) * GH_ + j] = hv;
            }
        }
    }
    target += nb; gsync(target);
    if (blockIdx.x == 0) {
        const float* hf = g_hbuf;
        for (int i = t; i < B_ * GH_; i += 1024) out_hn[i] = __ldcg(hf + i);
    }
}

// -------- per-token: normalize rout, gram penalty, cosine sims --------
__global__ void __launch_bounds__(128) token_kernel(const float* __restrict__ expr,
                                                    float* __restrict__ cosO) {
    const int token = blockIdx.x;
    const int t = threadIdx.x, lane = t & 31, warp = t >> 5;
    __shared__ float sv[16 * 132];
    __shared__ float gm[16][17];
    __shared__ float pen_s[16];
    const float* rout = g_hs + (size_t)token * GH_;

    for (int e = warp; e < 16; e += 4) {
        float s = 0.f;
        for (int d = lane; d < 128; d += 32) { float v = rout[e * 128 + d]; s += v * v; }
        s = wsum(s);
        float inv = 1.f / fmaxf(sqrtf(s), 1e-12f);
        for (int d = lane; d < 128; d += 32) sv[e * 132 + d] = rout[e * 128 + d] * inv;
    }
    __syncthreads();
    for (int p = t; p < 256; p += 128) {
        int e = p >> 4, f = p & 15;
        float s = 0.f;
#pragma unroll 8
        for (int k = 0; k < 128; k++) s += sv[e * 132 + k] * sv[f * 132 + k];
        gm[e][f] = s;
    }
    __syncthreads();
    if (t < 16) {
        float s2 = 0.f;
        for (int f = 0; f < 16; f++) {
            float d = gm[t][f] - (t == f ? 1.f : 0.f);
            s2 += d * d;
        }
        float nrm = fmaxf(sqrtf(s2), 1e-12f);
        pen_s[t] = s2 / (nrm * nrm);
    }
    __syncthreads();
    if (t == 0) {
        float s = 0.f;
        for (int e = 0; e < 16; e++) s += pen_s[e];
        g_pen[token] = s;
    }
    for (int e = warp; e < 16; e += 4) {
        float dot = 0.f, ss = 0.f, rs = 0.f;
        for (int d = lane; d < 128; d += 32) {
            float ev = expr[(size_t)token * GH_ + e * 128 + d];
            float rv = sv[e * 132 + d];
            dot += ev * rv; ss += ev * ev; rs += rv * rv;
        }
        dot = wsum(dot); ss = wsum(ss); rs = wsum(rs);
        if (lane == 0) {
            float en = fmaxf(sqrtf(ss), 1e-8f);
            float rn = fmaxf(sqrtf(rs), 1e-8f);
            cosO[token * 16 + e] = 1.f - dot / (en * rn);
        }
    }
}

// -------- penalty mean + load-balance adjustment --------
__global__ void finalize_kernel(const float* __restrict__ ema, float* __restrict__ out) {
    __shared__ float red[256];
    int t = threadIdx.x;
    float s = 0.f;
    for (int i = t; i < NTOK; i += 256) s += g_pen[i];
    red[t] = s; __syncthreads();
    for (int o = 128; o > 0; o >>= 1) { if (t < o) red[t] += red[t + o]; __syncthreads(); }
    if (t == 0) {
        float pen = red[0] / (float)NTOK;
        g_scal[0] = pen;
        out[O_PEN] = pen;
        float tot = 0.f;
        for (int e = 0; e < 16; e++) tot += ema[e];
        for (int e = 0; e < 16; e++) {
            float sc = (tot > 0.f) ? ema[e] / fmaxf(tot, 1e-12f) : 0.f;
            g_scal[1 + e] = sc * 0.01f * 16.f;
        }
    }
}

// -------- top-2 + softmax + adjustment --------
__global__ void topk_kernel(const float* __restrict__ cosv, float* __restrict__ out) {
    int token = blockIdx.x * blockDim.x + threadIdx.x;
    if (token >= NTOK) return;
    float mul = 1.f + g_scal[0];
    float dv[16];
#pragma unroll
    for (int e = 0; e < 16; e++) dv[e] = cosv[token * 16 + e] * mul;
    int i0 = 0; float v0 = dv[0];
#pragma unroll
    for (int e = 1; e < 16; e++) if (dv[e] > v0) { v0 = dv[e]; i0 = e; }
    int i1 = (i0 == 0) ? 1 : 0; float v1 = dv[i1];
#pragma unroll
    for (int e = 0; e < 16; e++) if (e != i0 && dv[e] > v1) { v1 = dv[e]; i1 = e; }
    float e1  = expf(v1 - v0);
    float inv = 1.f / (1.f + e1);
    out[O_MULT + token * 2 + 0] = inv - g_scal[1 + i0];
    out[O_MULT + token * 2 + 1] = e1 * inv - g_scal[1 + i1];
    out[O_SEL + token * 2 + 0] = (float)i0;
    out[O_SEL + token * 2 + 1] = (float)i1;
}

__global__ void wloss_reduce_kernel(float* __restrict__ out) {
    __shared__ float red[256];
    int t = threadIdx.x;
    float s = g_losspart[t];
    red[t] = s; __syncthreads();
    for (int o = 128; o > 0; o >>= 1) { if (t < o) red[t] += red[t + o]; __syncthreads(); }
    if (t == 0) out[O_LOSS] = red[0] / ((float)GH_ * (float)GH_);
}

// -------- host --------
extern "C" void kernel_launch(void* const* d_in, const int* in_sizes, int n_in,
                              void* d_out, int out_size) {
    const float* x      = (const float*)d_in[0];
    const float* hn     = (const float*)d_in[1];
    const float* w_ih   = (const float*)d_in[2];
    const float* w_hh   = (const float*)d_in[3];
    const float* w_expr = (const float*)d_in[4];
    const float* ema    = (const float*)d_in[5];
    float* out = (float*)d_out;

    void* p = 0;
    cudaGetSymbolAddress(&p, g_xi);  float* xi = (float*)p;
    __nv_bfloat16 *xh, *xl, *wih_h, *wih_l, *weT_h, *weT_l;
    cudaGetSymbolAddress(&p, g_xh);    xh = (__nv_bfloat16*)p;
    cudaGetSymbolAddress(&p, g_xl);    xl = (__nv_bfloat16*)p;
    cudaGetSymbolAddress(&p, g_wih_h); wih_h = (__nv_bfloat16*)p;
    cudaGetSymbolAddress(&p, g_wih_l); wih_l = (__nv_bfloat16*)p;
    cudaGetSymbolAddress(&p, g_weT_h); weT_h = (__nv_bfloat16*)p;
    cudaGetSymbolAddress(&p, g_weT_l); weT_l = (__nv_bfloat16*)p;

    static int smem_set = 0;
    if (!smem_set) {
        cudaFuncSetAttribute(mma_gemm_kernel<0>, cudaFuncAttributeMaxDynamicSharedMemorySize, SMTOT);
        cudaFuncSetAttribute(mma_gemm_kernel<1>, cudaFuncAttributeMaxDynamicSharedMemorySize, SMTOT);
        smem_set = 1;
    }

    init_kernel<<<32, 256>>>(hn);

    split_kernel<<<(NTOK * H_ / 4 + 255) / 256, 256>>>(x, xh, xl, NTOK * H_ / 4);
    split_kernel<<<(G3_ * H_ / 4 + 255) / 256, 256>>>(w_ih, wih_h, wih_l, G3_ * H_ / 4);
    tsplit_kernel<<<dim3(GH_ / 32, H_ / 32), dim3(32, 8)>>>(w_expr, weT_h, weT_l);

    // xi = x @ w_ih^T : [2048 x 6144]
    mma_gemm_kernel<0><<<dim3(G3_ / 128, NTOK / 128), 256, SMTOT>>>(
        xh, xl, wih_h, wih_l, xi, G3_, H_);
    // expr = x @ w_expr = x @ (w_expr^T)^T : [2048 x 2048]
    mma_gemm_kernel<0><<<dim3(GH_ / 128, NTOK / 128), 256, SMTOT>>>(
        xh, xl, weT_h, weT_l, out + O_EXPR, GH_, H_);

    gru_kernel<<<152, 1024>>>(w_hh, out + O_HN);

    token_kernel<<<NTOK, 128>>>(out + O_EXPR, out + O_COS);
    finalize_kernel<<<1, 256>>>(ema, out);
    topk_kernel<<<8, 256>>>(out + O_COS, out);

    // wloss: G = (w_expr^T) @ (w_expr^T)^T = W^T W : [2048 x 2048]
    mma_gemm_kernel<1><<<dim3(16, 16), 256, SMTOT>>>(
        weT_h, weT_l, weT_h, weT_l, nullptr, GH_, H_);
    wloss_reduce_kernel<<<1, 256>>>(out);
}